// round 2
// baseline (speedup 1.0000x reference)
#include <cuda_runtime.h>
#include <cstdint>

#define EPSF 1e-5f
#define HW 3136                 // 56*56
#define M_TOT 100352            // 32*56*56
#define KW_ELEM 589824          // 256*256*3*3

// ---------------- static device scratch (no runtime allocation) ----------------
__device__ int     g_maxbits[2];
__device__ uint8_t g_wq1[256 * 2304];     // int8 weights*3, layout [co][tap][ci]
__device__ uint8_t g_wq2[256 * 2304];
__device__ uint8_t g_act0[(size_t)M_TOT * 256];  // uint8 acts*3, NHWC
__device__ uint8_t g_act1[(size_t)M_TOT * 256];

// ---------------- init: zero the max reduction cells ----------------
__global__ void init_kernel() {
    g_maxbits[0] = 0;
    g_maxbits[1] = 0;
}

// ---------------- max |tanh(w)| per weight tensor ----------------
__global__ void wmax_kernel(const float* __restrict__ w1, const float* __restrict__ w2) {
    const float* w = blockIdx.y ? w2 : w1;
    float mx = 0.f;
    for (int i = blockIdx.x * blockDim.x + threadIdx.x; i < KW_ELEM;
         i += gridDim.x * blockDim.x)
        mx = fmaxf(mx, fabsf(tanhf(w[i])));
#pragma unroll
    for (int o = 16; o; o >>= 1)
        mx = fmaxf(mx, __shfl_xor_sync(0xffffffffu, mx, o));
    if ((threadIdx.x & 31) == 0)
        atomicMax(&g_maxbits[blockIdx.y], __float_as_int(mx));  // mx >= 0: int order == float order
}

// ---------------- weight quantize (*3, int8) + reorder OIHW -> [co][tap][ci] ----------------
__global__ void wquant_kernel(const float* __restrict__ w1, const float* __restrict__ w2) {
    int which = blockIdx.y;
    const float* w = which ? w2 : w1;
    uint8_t* dst = which ? g_wq2 : g_wq1;
    float mx = __int_as_float(g_maxbits[which]);
    float s = 1.f / (2.f * mx);
    int i = blockIdx.x * blockDim.x + threadIdx.x;
    if (i >= KW_ELEM) return;
    // i indexes OIHW: w[co][ci][kh][kw]
    float wn = tanhf(w[i]) * s + 0.5f;          // in [0,1]
    int q = (int)rintf(wn * 3.f);               // round-half-even, matches jnp.round
    int v = 2 * q - 3;                          // {-3,-1,1,3} = 3 * weight_quant
    int co = i / 2304;
    int r = i % 2304;
    int ci = r / 9;
    int tap = r % 9;                            // kh*3+kw
    dst[co * 2304 + tap * 256 + ci] = (uint8_t)(int8_t)v;
}

// ---------------- BN1 + ReLU + act quant (*3) + NCHW -> NHWC uint8 ----------------
__global__ void actprep_kernel(const float* __restrict__ x,
                               const float* __restrict__ g1, const float* __restrict__ b1,
                               const float* __restrict__ m1, const float* __restrict__ v1) {
    __shared__ __align__(16) uint8_t tile[56 * 260];   // [xx][c], padded row stride 260
    int nb = blockIdx.x;            // 0 .. 32*56-1
    int n = nb / 56, y = nb % 56;
    const float* xr = x + (size_t)n * 256 * HW + y * 56;
    for (int idx = threadIdx.x; idx < 256 * 56; idx += blockDim.x) {
        int c = idx / 56, xx = idx % 56;
        float iv = g1[c] / sqrtf(v1[c] + EPSF);
        float h = xr[(size_t)c * HW + xx] * iv + (b1[c] - m1[c] * iv);
        h = fminf(fmaxf(h, 0.f), 1.f);
        tile[xx * 260 + c] = (uint8_t)(int)rintf(h * 3.f);   // {0,1,2,3}
    }
    __syncthreads();
    uint32_t* o = (uint32_t*)(g_act0 + (size_t)((n * 56 + y) * 56) * 256);
    for (int idx = threadIdx.x; idx < 56 * 64; idx += blockDim.x) {
        int xx = idx >> 6, cq = idx & 63;
        o[xx * 64 + cq] = *(const uint32_t*)&tile[xx * 260 + cq * 4];
    }
}

// ---------------- implicit-GEMM conv3x3 via dp4a ----------------
// CTA: 128 pixels x 256 output channels.  K = 9 taps * 256 ci, staged 64 ci at a time (36 steps).
// phase 1: A=g_act0, B=g_wq1, epilogue BN2+ReLU+quant -> g_act1
// phase 2: A=g_act1, B=g_wq2, epilogue /9 + residual -> out (fp32 NCHW)
__global__ __launch_bounds__(512, 1)
void conv_kernel(int phase,
                 const float* __restrict__ g2, const float* __restrict__ b2,
                 const float* __restrict__ m2, const float* __restrict__ v2,
                 const float* __restrict__ xin, float* __restrict__ out) {
    __shared__ __align__(16) int As[2][16][128];   // [buf][kk][px]  16KB
    __shared__ __align__(16) int Bs[2][16][256];   // [buf][kk][co]  32KB

    const uint8_t* __restrict__ Ag = (phase == 1) ? g_act0 : g_act1;
    const uint8_t* __restrict__ Bg = (phase == 1) ? g_wq1 : g_wq2;

    const int t = threadIdx.x;

    // ---- A loader mapping: 128 rows x 64B, 512 threads -> 1x int4 each
    const int arow = t >> 2, aq = t & 3;
    const int am = blockIdx.x * 128 + arow;
    const int an = am / HW;
    const int ar = am % HW;
    const int ay = ar / 56, ax = ar % 56;

    // ---- B loader mapping: 256 rows x 64B, 512 threads -> 2x int4 each
    const int brow = t >> 1, bh = t & 1;
    const uint8_t* __restrict__ bbase = Bg + brow * 2304;

    int acc[2][2][4][4];
#pragma unroll
    for (int a = 0; a < 2; a++)
#pragma unroll
        for (int b = 0; b < 2; b++)
#pragma unroll
            for (int i = 0; i < 4; i++)
#pragma unroll
                for (int j = 0; j < 4; j++) acc[a][b][i][j] = 0;

    int4 la, lb0, lb1;

    auto LDG = [&](int s) {
        int tap = s >> 2, kc = s & 3;
        int yy = ay + tap / 3 - 1;
        int xx = ax + tap % 3 - 1;
        if (yy >= 0 && yy < 56 && xx >= 0 && xx < 56)
            la = *(const int4*)(Ag + (size_t)(((an * 56 + yy) * 56 + xx)) * 256 +
                                kc * 64 + aq * 16);
        else
            la = make_int4(0, 0, 0, 0);
        const uint8_t* bp = bbase + tap * 256 + kc * 64 + bh * 32;
        lb0 = *(const int4*)bp;
        lb1 = *(const int4*)(bp + 16);
    };
    auto STS = [&](int buf) {
        As[buf][aq * 4 + 0][arow] = la.x;
        As[buf][aq * 4 + 1][arow] = la.y;
        As[buf][aq * 4 + 2][arow] = la.z;
        As[buf][aq * 4 + 3][arow] = la.w;
        int kb = bh * 8;
        Bs[buf][kb + 0][brow] = lb0.x;
        Bs[buf][kb + 1][brow] = lb0.y;
        Bs[buf][kb + 2][brow] = lb0.z;
        Bs[buf][kb + 3][brow] = lb0.w;
        Bs[buf][kb + 4][brow] = lb1.x;
        Bs[buf][kb + 5][brow] = lb1.y;
        Bs[buf][kb + 6][brow] = lb1.z;
        Bs[buf][kb + 7][brow] = lb1.w;
    };

    const int tpx = t & 15;      // pixel group: px = {0,64} + tpx*4 + i
    const int tco = t >> 4;      // co group (0..31): co = {0,128} + tco*4 + j

    auto COMP = [&](int buf) {
#pragma unroll
        for (int kk = 0; kk < 16; kk++) {
            int4 a0 = *(const int4*)&As[buf][kk][tpx * 4];
            int4 a1 = *(const int4*)&As[buf][kk][64 + tpx * 4];
            int4 b0 = *(const int4*)&Bs[buf][kk][tco * 4];
            int4 b1 = *(const int4*)&Bs[buf][kk][128 + tco * 4];
            int av[2][4] = {{a0.x, a0.y, a0.z, a0.w}, {a1.x, a1.y, a1.z, a1.w}};
            int bv[2][4] = {{b0.x, b0.y, b0.z, b0.w}, {b1.x, b1.y, b1.z, b1.w}};
#pragma unroll
            for (int ia = 0; ia < 2; ia++)
#pragma unroll
                for (int jb = 0; jb < 2; jb++)
#pragma unroll
                    for (int i = 0; i < 4; i++)
#pragma unroll
                        for (int j = 0; j < 4; j++)
                            acc[ia][jb][i][j] =
                                __dp4a(av[ia][i], bv[jb][j], acc[ia][jb][i][j]);
        }
    };

    LDG(0);
    STS(0);
    __syncthreads();
#pragma unroll 1
    for (int s = 0; s < 36; s++) {
        if (s < 35) LDG(s + 1);
        COMP(s & 1);
        if (s < 35) STS((s + 1) & 1);   // writes the other buffer; prior readers synced last iter
        __syncthreads();
    }

    // ---------------- epilogue ----------------
    const int pmBase = blockIdx.x * 128;
    if (phase == 1) {
#pragma unroll
        for (int jb = 0; jb < 2; jb++) {
            float inv[4], bia[4];
#pragma unroll
            for (int j = 0; j < 4; j++) {
                int c = jb * 128 + tco * 4 + j;
                float iv = g2[c] / sqrtf(v2[c] + EPSF);
                inv[j] = iv;
                bia[j] = b2[c] - m2[c] * iv;
            }
#pragma unroll
            for (int ia = 0; ia < 2; ia++)
#pragma unroll
                for (int i = 0; i < 4; i++) {
                    int pm = pmBase + ia * 64 + tpx * 4 + i;
                    uchar4 pk;
                    float h;
                    h = (float)acc[ia][jb][i][0] * (1.f / 9.f) * inv[0] + bia[0];
                    h = fminf(fmaxf(h, 0.f), 1.f);
                    pk.x = (unsigned char)(int)rintf(h * 3.f);
                    h = (float)acc[ia][jb][i][1] * (1.f / 9.f) * inv[1] + bia[1];
                    h = fminf(fmaxf(h, 0.f), 1.f);
                    pk.y = (unsigned char)(int)rintf(h * 3.f);
                    h = (float)acc[ia][jb][i][2] * (1.f / 9.f) * inv[2] + bia[2];
                    h = fminf(fmaxf(h, 0.f), 1.f);
                    pk.z = (unsigned char)(int)rintf(h * 3.f);
                    h = (float)acc[ia][jb][i][3] * (1.f / 9.f) * inv[3] + bia[3];
                    h = fminf(fmaxf(h, 0.f), 1.f);
                    pk.w = (unsigned char)(int)rintf(h * 3.f);
                    *(uchar4*)(g_act1 + (size_t)pm * 256 + jb * 128 + tco * 4) = pk;
                }
        }
    } else {
#pragma unroll
        for (int ia = 0; ia < 2; ia++)
#pragma unroll
            for (int i = 0; i < 4; i++) {
                int pm = pmBase + ia * 64 + tpx * 4 + i;
                int nn = pm / HW;
                int rr = pm % HW;
#pragma unroll
                for (int jb = 0; jb < 2; jb++)
#pragma unroll
                    for (int j = 0; j < 4; j++) {
                        int c = jb * 128 + tco * 4 + j;
                        size_t idx = (size_t)(nn * 256 + c) * HW + rr;
                        out[idx] = (float)acc[ia][jb][i][j] * (1.f / 9.f) + xin[idx];
                    }
            }
    }
}

// ---------------- launch ----------------
extern "C" void kernel_launch(void* const* d_in, const int* in_sizes, int n_in,
                              void* d_out, int out_size) {
    const float* x  = (const float*)d_in[0];
    const float* w1 = (const float*)d_in[1];
    const float* w2 = (const float*)d_in[2];
    const float* g1 = (const float*)d_in[3];
    const float* b1 = (const float*)d_in[4];
    const float* m1 = (const float*)d_in[5];
    const float* v1 = (const float*)d_in[6];
    const float* g2 = (const float*)d_in[7];
    const float* b2 = (const float*)d_in[8];
    const float* m2 = (const float*)d_in[9];
    const float* v2 = (const float*)d_in[10];
    float* out = (float*)d_out;

    (void)in_sizes; (void)n_in; (void)out_size;

    init_kernel<<<1, 1>>>();
    wmax_kernel<<<dim3(128, 2), 256>>>(w1, w2);
    wquant_kernel<<<dim3(2304, 2), 256>>>(w1, w2);
    actprep_kernel<<<32 * 56, 256>>>(x, g1, b1, m1, v1);
    conv_kernel<<<784, 512>>>(1, g2, b2, m2, v2, x, out);
    conv_kernel<<<784, 512>>>(2, g2, b2, m2, v2, x, out);
}

// round 4
// speedup vs baseline: 1.1294x; 1.1294x over previous
#include <cuda_runtime.h>
#include <cstdint>

#define EPSF 1e-5f
#define HW 3136                 // 56*56
#define M_TOT 100352            // 32*56*56
#define KW_ELEM 589824          // 256*256*3*3

// int8 code tables (byte i = value for q=i), used with __byte_perm
#define WQ_TABLE  0x0301FFFDu   // q=0..3 -> -3,-1,1,3
#define ACT_TABLE 0x03020100u   // q=0..3 ->  0, 1,2,3

// ---------------- static device scratch ----------------
__device__ int g_maxbits[2];
__device__ __align__(128) uint8_t g_wq1[256 * 2304];      // int8 weights*3, [co][tap][ci]
__device__ __align__(128) uint8_t g_wq2[256 * 2304];
__device__ __align__(128) uint8_t g_act0[(size_t)M_TOT * 256];   // int8 acts*3, NHWC
__device__ __align__(128) uint8_t g_act1[(size_t)M_TOT * 256];

__device__ __forceinline__ uint32_t smem_u32(const void* p) {
    uint32_t a;
    asm("{ .reg .u64 t; cvta.to.shared.u64 t, %1; cvt.u32.u64 %0, t; }" : "=r"(a) : "l"(p));
    return a;
}

__device__ __forceinline__ void ldsm_x4(uint32_t& f0, uint32_t& f1, uint32_t& f2,
                                        uint32_t& f3, uint32_t addr) {
    asm volatile("ldmatrix.sync.aligned.m8n8.x4.shared.b16 {%0,%1,%2,%3}, [%4];"
                 : "=r"(f0), "=r"(f1), "=r"(f2), "=r"(f3) : "r"(addr));
}

__device__ __forceinline__ void imma16832(int* c, const uint32_t* a, uint32_t b0, uint32_t b1) {
    asm volatile(
        "mma.sync.aligned.m16n8k32.row.col.s32.s8.s8.s32 "
        "{%0,%1,%2,%3}, {%4,%5,%6,%7}, {%8,%9}, {%0,%1,%2,%3};"
        : "+r"(c[0]), "+r"(c[1]), "+r"(c[2]), "+r"(c[3])
        : "r"(a[0]), "r"(a[1]), "r"(a[2]), "r"(a[3]), "r"(b0), "r"(b1));
}

// ---------------- prep kernels ----------------
__global__ void init_kernel() {
    g_maxbits[0] = 0;
    g_maxbits[1] = 0;
}

__global__ void wmax_kernel(const float* __restrict__ w1, const float* __restrict__ w2) {
    const float* w = blockIdx.y ? w2 : w1;
    float mx = 0.f;
    for (int i = blockIdx.x * blockDim.x + threadIdx.x; i < KW_ELEM;
         i += gridDim.x * blockDim.x)
        mx = fmaxf(mx, fabsf(tanhf(w[i])));
#pragma unroll
    for (int o = 16; o; o >>= 1)
        mx = fmaxf(mx, __shfl_xor_sync(0xffffffffu, mx, o));
    if ((threadIdx.x & 31) == 0)
        atomicMax(&g_maxbits[blockIdx.y], __float_as_int(mx));
}

__global__ void wquant_kernel(const float* __restrict__ w1, const float* __restrict__ w2) {
    int which = blockIdx.y;
    const float* w = which ? w2 : w1;
    uint8_t* dst = which ? g_wq2 : g_wq1;
    float mx = __int_as_float(g_maxbits[which]);
    float s = 1.f / (2.f * mx);
    int i = blockIdx.x * blockDim.x + threadIdx.x;
    if (i >= KW_ELEM) return;
    float wn = tanhf(w[i]) * s + 0.5f;
    int q = (int)rintf(wn * 3.f);
    int co = i / 2304;
    int r = i % 2304;
    int ci = r / 9;
    int tap = r % 9;
    dst[co * 2304 + tap * 256 + ci] = (uint8_t)__byte_perm(WQ_TABLE, 0, q);
}

// BN1 + ReLU + 2-bit quant (*3) + NCHW -> NHWC int8
__global__ void actprep_kernel(const float* __restrict__ x,
                               const float* __restrict__ g1, const float* __restrict__ b1,
                               const float* __restrict__ m1, const float* __restrict__ v1) {
    __shared__ float ivs[256], bis[256];
    __shared__ __align__(16) uint8_t tile[56 * 260];
    int t = threadIdx.x;
    if (t < 256) {
        float iv = g1[t] / sqrtf(v1[t] + EPSF);
        ivs[t] = iv;
        bis[t] = b1[t] - m1[t] * iv;
    }
    __syncthreads();
    int nb = blockIdx.x;
    int n = nb / 56, y = nb % 56;
    const float* xr = x + (size_t)n * 256 * HW + y * 56;
    for (int idx = t; idx < 256 * 56; idx += blockDim.x) {
        int c = idx / 56, xx = idx % 56;
        float h = xr[(size_t)c * HW + xx] * ivs[c] + bis[c];
        h = fminf(fmaxf(h, 0.f), 1.f);
        int q = (int)rintf(h * 3.f);
        tile[xx * 260 + c] = (uint8_t)__byte_perm(ACT_TABLE, 0, q);
    }
    __syncthreads();
    uint32_t* o = (uint32_t*)(g_act0 + (size_t)((n * 56 + y) * 56) * 256);
    for (int idx = t; idx < 56 * 64; idx += blockDim.x) {
        int xx = idx >> 6, cq = idx & 63;
        o[xx * 64 + cq] = *(const uint32_t*)&tile[xx * 260 + cq * 4];
    }
}

// ---------------- implicit-GEMM conv3x3 via mma.sync (IMMA m16n8k32 s8) ----------------
// CTA: 128 px x 256 co.  K = 2304, 36 double-buffered stages of 64B (tap = s/4, quarter = s%4).
// 16 warps, each a 32(M) x 64(N) warp tile -> 4(M) x 4(N) warp grid.
// SMEM rows padded to 80B so ldmatrix row addresses land on 8 distinct bank groups.
// Layout: A0@0 (10240) A1@10240  B0@20480 (20480) B1@40960  ivs@61440 bis@62464; total 63488
#define CONV_SMEM 63488
#define A_STRIDE 80
#define B_STRIDE 80
#define A_BUF 10240
#define B_BASE 20480
#define B_BUF 20480

__global__ __launch_bounds__(512, 1)
void conv_imma_kernel(int phase,
                      const float* __restrict__ g2, const float* __restrict__ b2,
                      const float* __restrict__ m2, const float* __restrict__ v2,
                      const float* __restrict__ xin, float* __restrict__ out) {
    extern __shared__ __align__(128) uint8_t smem[];
    float* ivs = (float*)(smem + 61440);
    float* bis = (float*)(smem + 62464);
    const uint32_t sbase = smem_u32(smem);

    const uint8_t* __restrict__ Ag = (phase == 1) ? g_act0 : g_act1;
    const uint8_t* __restrict__ Bg = (phase == 1) ? g_wq1 : g_wq2;

    const int t = threadIdx.x;
    const int wid = t >> 5, lid = t & 31;
    const int wm = wid & 3, wn = wid >> 2;       // warp grid 4(M) x 4(N)
    const int g = lid >> 2, tig = lid & 3;

    if (phase == 1 && t < 256) {
        float iv = g2[t] / sqrtf(v2[t] + EPSF);
        ivs[t] = iv;
        bis[t] = b2[t] - m2[t] * iv;
    }

    // ---- global loader mappings
    const int arow = t >> 2, aq = t & 3;         // A: 128 rows x 4 x 16B
    const int pm = blockIdx.x * 128 + arow;
    const int an = pm / HW;
    const int ar = pm - an * HW;
    const int ay = ar / 56, ax = ar - (ar / 56) * 56;
    const int brow = t >> 1, bh = t & 1;         // B: 256 rows x 2 x 32B
    const uint8_t* __restrict__ bb = Bg + brow * 2304;

    int4 la, lb0, lb1;
    auto LDG = [&](int s) {
        int tap = s >> 2, q = s & 3;
        int ty = tap / 3, tx = tap - ty * 3;
        int yy = ay + ty - 1, xx = ax + tx - 1;
        if (yy >= 0 && yy < 56 && xx >= 0 && xx < 56)
            la = *(const int4*)(Ag + (size_t)((an * 56 + yy) * 56 + xx) * 256 + q * 64 + aq * 16);
        else
            la = make_int4(0, 0, 0, 0);
        const uint8_t* bp = bb + tap * 256 + q * 64 + bh * 32;
        lb0 = ((const int4*)bp)[0];
        lb1 = ((const int4*)bp)[1];
    };
    auto STS = [&](int buf) {
        *(int4*)(smem + buf * A_BUF + arow * A_STRIDE + aq * 16) = la;
        uint8_t* bq = smem + B_BASE + buf * B_BUF + brow * B_STRIDE + bh * 32;
        ((int4*)bq)[0] = lb0;
        ((int4*)bq)[1] = lb1;
    };

    // ---- ldmatrix per-lane address offsets (within a buffer)
    // A, m-tile i: row = wm*32 + i*16 + (lid&15), 16B col = (lid>>4) (+ ks*2)
    uint32_t aoff[2];
#pragma unroll
    for (int i = 0; i < 2; i++)
        aoff[i] = (uint32_t)((wm * 32 + i * 16 + (lid & 15)) * A_STRIDE + (lid >> 4) * 16);
    // B, pair j: n = wn*64 + j*16 + (lid&7) + ((lid>>4)&1)*8 ; 16B col = (lid>>3)&1 (+ ks*2)
    uint32_t boff[4];
#pragma unroll
    for (int j = 0; j < 4; j++)
        boff[j] = (uint32_t)((wn * 64 + j * 16 + (lid & 7) + ((lid >> 4) & 1) * 8) * B_STRIDE +
                             ((lid >> 3) & 1) * 16);

    int acc[2][8][4];
#pragma unroll
    for (int i = 0; i < 2; i++)
#pragma unroll
        for (int n = 0; n < 8; n++)
#pragma unroll
            for (int c = 0; c < 4; c++) acc[i][n][c] = 0;

    auto COMP = [&](int buf) {
        uint32_t ab = sbase + buf * A_BUF;
        uint32_t bbs = sbase + B_BASE + buf * B_BUF;
#pragma unroll
        for (int ks = 0; ks < 2; ks++) {
            uint32_t afr[2][4];
#pragma unroll
            for (int i = 0; i < 2; i++)
                ldsm_x4(afr[i][0], afr[i][1], afr[i][2], afr[i][3],
                        ab + aoff[i] + ks * 32);
#pragma unroll
            for (int j = 0; j < 4; j++) {
                uint32_t b0, b1, b2_, b3;
                ldsm_x4(b0, b1, b2_, b3, bbs + boff[j] + ks * 32);
#pragma unroll
                for (int i = 0; i < 2; i++) {
                    imma16832(acc[i][j * 2 + 0], afr[i], b0, b1);
                    imma16832(acc[i][j * 2 + 1], afr[i], b2_, b3);
                }
            }
        }
    };

    LDG(0);
    STS(0);
    __syncthreads();
#pragma unroll 1
    for (int s = 0; s < 36; s++) {
        if (s < 35) LDG(s + 1);
        COMP(s & 1);
        if (s < 35) STS((s + 1) & 1);
        __syncthreads();
    }

    // ---------------- epilogue (fragment-direct stores) ----------------
    // thread owns rows blk*128 + wm*32 + i*16 + g (+8), cols wn*64 + nt*8 + tig*2 (+1)
    const int pm0 = blockIdx.x * 128 + wm * 32 + g;
    const int c0 = wn * 64 + tig * 2;

    if (phase == 1) {
#pragma unroll
        for (int i = 0; i < 2; i++)
#pragma unroll
            for (int h = 0; h < 2; h++) {
                int px = pm0 + i * 16 + h * 8;
                uint8_t* dst = g_act1 + (size_t)px * 256 + c0;
#pragma unroll
                for (int nt = 0; nt < 8; nt++) {
                    int c = c0 + nt * 8;
                    float v0 = (float)acc[i][nt][h * 2 + 0] * (1.f / 9.f) * ivs[c] + bis[c];
                    float v1 = (float)acc[i][nt][h * 2 + 1] * (1.f / 9.f) * ivs[c + 1] + bis[c + 1];
                    v0 = fminf(fmaxf(v0, 0.f), 1.f);
                    v1 = fminf(fmaxf(v1, 0.f), 1.f);
                    int q0 = (int)rintf(v0 * 3.f);
                    int q1 = (int)rintf(v1 * 3.f);
                    uchar2 pk;
                    pk.x = (uint8_t)__byte_perm(ACT_TABLE, 0, q0);
                    pk.y = (uint8_t)__byte_perm(ACT_TABLE, 0, q1);
                    *(uchar2*)(dst + nt * 8) = pk;
                }
            }
    } else {
#pragma unroll
        for (int i = 0; i < 2; i++)
#pragma unroll
            for (int h = 0; h < 2; h++) {
                int px = pm0 + i * 16 + h * 8;
                int nn = px / HW;
                int rr = px - nn * HW;
                const float* xp = xin + (size_t)nn * 256 * HW + rr;
                float* op = out + (size_t)nn * 256 * HW + rr;
#pragma unroll
                for (int nt = 0; nt < 8; nt++) {
                    int c = c0 + nt * 8;
                    size_t o0 = (size_t)c * HW;
                    size_t o1 = (size_t)(c + 1) * HW;
                    op[o0] = (float)acc[i][nt][h * 2 + 0] * (1.f / 9.f) + xp[o0];
                    op[o1] = (float)acc[i][nt][h * 2 + 1] * (1.f / 9.f) + xp[o1];
                }
            }
    }
}

// ---------------- launch ----------------
extern "C" void kernel_launch(void* const* d_in, const int* in_sizes, int n_in,
                              void* d_out, int out_size) {
    const float* x  = (const float*)d_in[0];
    const float* w1 = (const float*)d_in[1];
    const float* w2 = (const float*)d_in[2];
    const float* g1 = (const float*)d_in[3];
    const float* b1 = (const float*)d_in[4];
    const float* m1 = (const float*)d_in[5];
    const float* v1 = (const float*)d_in[6];
    const float* g2 = (const float*)d_in[7];
    const float* b2 = (const float*)d_in[8];
    const float* m2 = (const float*)d_in[9];
    const float* v2 = (const float*)d_in[10];
    float* out = (float*)d_out;
    (void)in_sizes; (void)n_in; (void)out_size;

    cudaFuncSetAttribute(conv_imma_kernel,
                         cudaFuncAttributeMaxDynamicSharedMemorySize, CONV_SMEM);

    init_kernel<<<1, 1>>>();
    wmax_kernel<<<dim3(128, 2), 256>>>(w1, w2);
    wquant_kernel<<<dim3(2304, 2), 256>>>(w1, w2);
    actprep_kernel<<<32 * 56, 256>>>(x, g1, b1, m1, v1);
    conv_imma_kernel<<<784, 512, CONV_SMEM>>>(1, g2, b2, m2, v2, x, out);
    conv_imma_kernel<<<784, 512, CONV_SMEM>>>(2, g2, b2, m2, v2, x, out);
}

// round 5
// speedup vs baseline: 2.4830x; 2.1986x over previous
#include <cuda_runtime.h>
#include <cstdint>

#define EPSF 1e-5f
#define HW 3136                 // 56*56
#define M_TOT 100352            // 32*56*56
#define KW_ELEM 589824          // 256*256*3*3

// fp16 bit patterns
__device__ __constant__ uint16_t ACTH[4] = {0x0000, 0x3C00, 0x4000, 0x4200};  // 0,1,2,3
__device__ __constant__ uint16_t WQH[4]  = {0xC200, 0xBC00, 0x3C00, 0x4200};  // -3,-1,1,3

// ---------------- static device scratch ----------------
__device__ int g_maxbits[2];
__device__ __align__(128) uint16_t g_wq1[256 * 2304];     // fp16 weights*3, [co][tap][ci]
__device__ __align__(128) uint16_t g_wq2[256 * 2304];
__device__ __align__(128) uint16_t g_act0[(size_t)M_TOT * 256];  // fp16 acts*3, NHWC
__device__ __align__(128) uint16_t g_act1[(size_t)M_TOT * 256];

__device__ __forceinline__ uint32_t smem_u32(const void* p) {
    uint32_t a;
    asm("{ .reg .u64 t; cvta.to.shared.u64 t, %1; cvt.u32.u64 %0, t; }" : "=r"(a) : "l"(p));
    return a;
}

__device__ __forceinline__ void ldsm_x4(uint32_t& f0, uint32_t& f1, uint32_t& f2,
                                        uint32_t& f3, uint32_t addr) {
    asm volatile("ldmatrix.sync.aligned.m8n8.x4.shared.b16 {%0,%1,%2,%3}, [%4];"
                 : "=r"(f0), "=r"(f1), "=r"(f2), "=r"(f3) : "r"(addr));
}

__device__ __forceinline__ void hmma16816(float* c, const uint32_t* a, uint32_t b0, uint32_t b1) {
    asm volatile(
        "mma.sync.aligned.m16n8k16.row.col.f32.f16.f16.f32 "
        "{%0,%1,%2,%3}, {%4,%5,%6,%7}, {%8,%9}, {%0,%1,%2,%3};"
        : "+f"(c[0]), "+f"(c[1]), "+f"(c[2]), "+f"(c[3])
        : "r"(a[0]), "r"(a[1]), "r"(a[2]), "r"(a[3]), "r"(b0), "r"(b1));
}

// ---------------- prep kernels ----------------
__global__ void init_kernel() {
    g_maxbits[0] = 0;
    g_maxbits[1] = 0;
}

__global__ void wmax_kernel(const float* __restrict__ w1, const float* __restrict__ w2) {
    const float* w = blockIdx.y ? w2 : w1;
    float mx = 0.f;
    for (int i = blockIdx.x * blockDim.x + threadIdx.x; i < KW_ELEM;
         i += gridDim.x * blockDim.x)
        mx = fmaxf(mx, fabsf(tanhf(w[i])));
#pragma unroll
    for (int o = 16; o; o >>= 1)
        mx = fmaxf(mx, __shfl_xor_sync(0xffffffffu, mx, o));
    if ((threadIdx.x & 31) == 0)
        atomicMax(&g_maxbits[blockIdx.y], __float_as_int(mx));
}

__global__ void wquant_kernel(const float* __restrict__ w1, const float* __restrict__ w2) {
    int which = blockIdx.y;
    const float* w = which ? w2 : w1;
    uint16_t* dst = which ? g_wq2 : g_wq1;
    float mx = __int_as_float(g_maxbits[which]);
    float s = 1.f / (2.f * mx);
    int i = blockIdx.x * blockDim.x + threadIdx.x;
    if (i >= KW_ELEM) return;
    float wn = tanhf(w[i]) * s + 0.5f;
    int q = (int)rintf(wn * 3.f);
    int co = i / 2304;
    int r = i % 2304;
    int ci = r / 9;
    int tap = r % 9;
    dst[co * 2304 + tap * 256 + ci] = WQH[q];
}

// BN1 + ReLU + 2-bit quant (*3) + NCHW -> NHWC fp16
__global__ void actprep_kernel(const float* __restrict__ x,
                               const float* __restrict__ g1, const float* __restrict__ b1,
                               const float* __restrict__ m1, const float* __restrict__ v1) {
    __shared__ float ivs[256], bis[256];
    __shared__ __align__(16) uint16_t tile[56 * 264];
    int t = threadIdx.x;
    if (t < 256) {
        float iv = g1[t] / sqrtf(v1[t] + EPSF);
        ivs[t] = iv;
        bis[t] = b1[t] - m1[t] * iv;
    }
    __syncthreads();
    int nb = blockIdx.x;
    int n = nb / 56, y = nb % 56;
    const float* xr = x + (size_t)n * 256 * HW + y * 56;
    for (int idx = t; idx < 256 * 56; idx += blockDim.x) {
        int c = idx / 56, xx = idx % 56;
        float h = xr[(size_t)c * HW + xx] * ivs[c] + bis[c];
        h = fminf(fmaxf(h, 0.f), 1.f);
        int q = (int)rintf(h * 3.f);
        tile[xx * 264 + c] = ACTH[q];
    }
    __syncthreads();
    uint4* o = (uint4*)(g_act0 + (size_t)((n * 56 + y) * 56) * 256);
    for (int idx = t; idx < 56 * 32; idx += blockDim.x) {
        int xx = idx >> 5, qq = idx & 31;
        o[xx * 32 + qq] = *(const uint4*)&tile[xx * 264 + qq * 8];
    }
}

// ---------------- implicit-GEMM conv3x3 via mma.sync (HMMA m16n8k16 f16->f32) ----------------
// CTA: 128 px x 256 co.  K = 2304 ch, 36 double-buffered stages of 64 ch (tap=s/4, quarter=s%4).
// 16 warps, each a 32(M) x 64(N) warp tile.
// SMEM rows = 128B data padded to 144B (ldmatrix row addrs hit 8 distinct bank groups).
#define A_STRIDE 144
#define A_BUF 18432            // 128*144
#define B_BASE 36864
#define B_BUF 36864            // 256*144
#define IVS_OFF 110592
#define BIS_OFF 111616
#define CONV_SMEM 112640

__global__ __launch_bounds__(512, 1)
void conv_hmma_kernel(int phase,
                      const float* __restrict__ g2, const float* __restrict__ b2,
                      const float* __restrict__ m2, const float* __restrict__ v2,
                      const float* __restrict__ xin, float* __restrict__ out) {
    extern __shared__ __align__(128) uint8_t smem[];
    float* ivs = (float*)(smem + IVS_OFF);
    float* bis = (float*)(smem + BIS_OFF);
    const uint32_t sbase = smem_u32(smem);

    const uint16_t* __restrict__ Ag = (phase == 1) ? g_act0 : g_act1;
    const uint16_t* __restrict__ Bg = (phase == 1) ? g_wq1 : g_wq2;

    const int t = threadIdx.x;
    const int wid = t >> 5, lid = t & 31;
    const int wm = wid & 3, wn = wid >> 2;       // warp grid 4(M) x 4(N)
    const int g = lid >> 2, tig = lid & 3;

    if (phase == 1 && t < 256) {
        float iv = g2[t] / sqrtf(v2[t] + EPSF);
        ivs[t] = iv;
        bis[t] = b2[t] - m2[t] * iv;
    }

    // ---- global loader mappings
    const int arow = t >> 2, aq = t & 3;         // A: 128 rows x 4 x 32B
    const int pm = blockIdx.x * 128 + arow;
    const int an = pm / HW;
    const int ar = pm - an * HW;
    const int ay = ar / 56, ax = ar - (ar / 56) * 56;
    const int brow = t >> 1, bh = t & 1;         // B: 256 rows x 2 x 64B
    const uint16_t* __restrict__ bb = Bg + brow * 2304;

    int4 la0, la1, lb0, lb1, lb2, lb3;
    auto LDG = [&](int s) {
        int tap = s >> 2, q = s & 3;             // 64-ch quarter
        int ty = tap / 3, tx = tap - ty * 3;
        int yy = ay + ty - 1, xx = ax + tx - 1;
        if (yy >= 0 && yy < 56 && xx >= 0 && xx < 56) {
            const uint16_t* ap = Ag + (size_t)((an * 56 + yy) * 56 + xx) * 256 + q * 64 + aq * 16;
            la0 = ((const int4*)ap)[0];
            la1 = ((const int4*)ap)[1];
        } else {
            la0 = make_int4(0, 0, 0, 0);
            la1 = make_int4(0, 0, 0, 0);
        }
        const uint16_t* bp = bb + tap * 256 + q * 64 + bh * 32;
        lb0 = ((const int4*)bp)[0];
        lb1 = ((const int4*)bp)[1];
        lb2 = ((const int4*)bp)[2];
        lb3 = ((const int4*)bp)[3];
    };
    auto STS = [&](int buf) {
        uint8_t* aa = smem + buf * A_BUF + arow * A_STRIDE + aq * 32;
        ((int4*)aa)[0] = la0;
        ((int4*)aa)[1] = la1;
        uint8_t* bq = smem + B_BASE + buf * B_BUF + brow * A_STRIDE + bh * 64;
        ((int4*)bq)[0] = lb0;
        ((int4*)bq)[1] = lb1;
        ((int4*)bq)[2] = lb2;
        ((int4*)bq)[3] = lb3;
    };

    // ---- ldmatrix per-lane offsets (within buffer); per k-step add ks*32
    uint32_t aoff[2];
#pragma unroll
    for (int i = 0; i < 2; i++)
        aoff[i] = (uint32_t)((wm * 32 + i * 16 + (lid & 15)) * A_STRIDE + (lid >> 4) * 16);
    uint32_t boff[4];
#pragma unroll
    for (int j = 0; j < 4; j++)
        boff[j] = (uint32_t)((wn * 64 + j * 16 + (lid & 7) + ((lid >> 4) & 1) * 8) * A_STRIDE +
                             ((lid >> 3) & 1) * 16);

    float acc[2][8][4];
#pragma unroll
    for (int i = 0; i < 2; i++)
#pragma unroll
        for (int n = 0; n < 8; n++)
#pragma unroll
            for (int c = 0; c < 4; c++) acc[i][n][c] = 0.f;

    auto COMP = [&](int buf) {
        uint32_t ab = sbase + buf * A_BUF;
        uint32_t bbs = sbase + B_BASE + buf * B_BUF;
#pragma unroll
        for (int ks = 0; ks < 4; ks++) {         // 4 k-steps of 16 ch
            uint32_t afr[2][4];
#pragma unroll
            for (int i = 0; i < 2; i++)
                ldsm_x4(afr[i][0], afr[i][1], afr[i][2], afr[i][3],
                        ab + aoff[i] + ks * 32);
#pragma unroll
            for (int j = 0; j < 4; j++) {
                uint32_t m0, m1, m2_, m3;
                ldsm_x4(m0, m1, m2_, m3, bbs + boff[j] + ks * 32);
#pragma unroll
                for (int i = 0; i < 2; i++) {
                    hmma16816(acc[i][j * 2 + 0], afr[i], m0, m1);
                    hmma16816(acc[i][j * 2 + 1], afr[i], m2_, m3);
                }
            }
        }
    };

    LDG(0);
    STS(0);
    __syncthreads();
#pragma unroll 1
    for (int s = 0; s < 36; s++) {
        if (s < 35) LDG(s + 1);
        COMP(s & 1);
        if (s < 35) STS((s + 1) & 1);
        __syncthreads();
    }

    // ---------------- epilogue (fragment-direct stores) ----------------
    // thread owns rows blk*128 + wm*32 + i*16 + g (+8), cols wn*64 + nt*8 + tig*2 (+1)
    const int pm0 = blockIdx.x * 128 + wm * 32 + g;
    const int c0 = wn * 64 + tig * 2;

    if (phase == 1) {
#pragma unroll
        for (int i = 0; i < 2; i++)
#pragma unroll
            for (int h = 0; h < 2; h++) {
                int px = pm0 + i * 16 + h * 8;
                uint16_t* dst = g_act1 + (size_t)px * 256 + c0;
#pragma unroll
                for (int nt = 0; nt < 8; nt++) {
                    int c = c0 + nt * 8;
                    float v0 = acc[i][nt][h * 2 + 0] * (1.f / 9.f) * ivs[c] + bis[c];
                    float v1 = acc[i][nt][h * 2 + 1] * (1.f / 9.f) * ivs[c + 1] + bis[c + 1];
                    v0 = fminf(fmaxf(v0, 0.f), 1.f);
                    v1 = fminf(fmaxf(v1, 0.f), 1.f);
                    int q0 = (int)rintf(v0 * 3.f);
                    int q1 = (int)rintf(v1 * 3.f);
                    uint32_t pk = (uint32_t)ACTH[q0] | ((uint32_t)ACTH[q1] << 16);
                    *(uint32_t*)(dst + nt * 8) = pk;
                }
            }
    } else {
#pragma unroll
        for (int i = 0; i < 2; i++)
#pragma unroll
            for (int h = 0; h < 2; h++) {
                int px = pm0 + i * 16 + h * 8;
                int nn = px / HW;
                int rr = px - nn * HW;
                const float* xp = xin + (size_t)nn * 256 * HW + rr;
                float* op = out + (size_t)nn * 256 * HW + rr;
#pragma unroll
                for (int nt = 0; nt < 8; nt++) {
                    int c = c0 + nt * 8;
                    size_t o0 = (size_t)c * HW;
                    size_t o1 = (size_t)(c + 1) * HW;
                    op[o0] = acc[i][nt][h * 2 + 0] * (1.f / 9.f) + xp[o0];
                    op[o1] = acc[i][nt][h * 2 + 1] * (1.f / 9.f) + xp[o1];
                }
            }
    }
}

// ---------------- launch ----------------
extern "C" void kernel_launch(void* const* d_in, const int* in_sizes, int n_in,
                              void* d_out, int out_size) {
    const float* x  = (const float*)d_in[0];
    const float* w1 = (const float*)d_in[1];
    const float* w2 = (const float*)d_in[2];
    const float* g1 = (const float*)d_in[3];
    const float* b1 = (const float*)d_in[4];
    const float* m1 = (const float*)d_in[5];
    const float* v1 = (const float*)d_in[6];
    const float* g2 = (const float*)d_in[7];
    const float* b2 = (const float*)d_in[8];
    const float* m2 = (const float*)d_in[9];
    const float* v2 = (const float*)d_in[10];
    float* out = (float*)d_out;
    (void)in_sizes; (void)n_in; (void)out_size;

    cudaFuncSetAttribute(conv_hmma_kernel,
                         cudaFuncAttributeMaxDynamicSharedMemorySize, CONV_SMEM);

    init_kernel<<<1, 1>>>();
    wmax_kernel<<<dim3(128, 2), 256>>>(w1, w2);
    wquant_kernel<<<dim3(2304, 2), 256>>>(w1, w2);
    actprep_kernel<<<32 * 56, 256>>>(x, g1, b1, m1, v1);
    conv_hmma_kernel<<<784, 512, CONV_SMEM>>>(1, g2, b2, m2, v2, x, out);
    conv_hmma_kernel<<<784, 512, CONV_SMEM>>>(2, g2, b2, m2, v2, x, out);
}

// round 6
// speedup vs baseline: 2.5700x; 1.0350x over previous
#include <cuda_runtime.h>
#include <cstdint>

#define EPSF 1e-5f
#define HW 3136                 // 56*56
#define M_TOT 100352            // 32*56*56
#define KW_ELEM 589824          // 256*256*3*3

// e4m3 code tables (byte i = code for q=i), used with __byte_perm
#define WQ_TABLE  0x4438B8C4u   // q=0..3 -> -3,-1,1,3
#define ACT_TABLE 0x44403800u   // q=0..3 ->  0, 1,2,3

// ---------------- static device scratch ----------------
__device__ int g_maxbits[2];
__device__ __align__(128) uint8_t g_wq1[256 * 2304];      // e4m3 weights*3, [co][tap][ci]
__device__ __align__(128) uint8_t g_wq2[256 * 2304];
__device__ __align__(128) uint8_t g_act0[(size_t)M_TOT * 256];   // e4m3 acts*3, NHWC
__device__ __align__(128) uint8_t g_act1[(size_t)M_TOT * 256];

__device__ __forceinline__ uint32_t smem_u32(const void* p) {
    uint32_t a;
    asm("{ .reg .u64 t; cvta.to.shared.u64 t, %1; cvt.u32.u64 %0, t; }" : "=r"(a) : "l"(p));
    return a;
}

__device__ __forceinline__ void ldsm_x4(uint32_t& f0, uint32_t& f1, uint32_t& f2,
                                        uint32_t& f3, uint32_t addr) {
    asm volatile("ldmatrix.sync.aligned.m8n8.x4.shared.b16 {%0,%1,%2,%3}, [%4];"
                 : "=r"(f0), "=r"(f1), "=r"(f2), "=r"(f3) : "r"(addr));
}

__device__ __forceinline__ void qmma16832(float* c, const uint32_t* a, uint32_t b0, uint32_t b1) {
    asm volatile(
        "mma.sync.aligned.m16n8k32.row.col.f32.e4m3.e4m3.f32 "
        "{%0,%1,%2,%3}, {%4,%5,%6,%7}, {%8,%9}, {%0,%1,%2,%3};"
        : "+f"(c[0]), "+f"(c[1]), "+f"(c[2]), "+f"(c[3])
        : "r"(a[0]), "r"(a[1]), "r"(a[2]), "r"(a[3]), "r"(b0), "r"(b1));
}

// ---------------- prep kernels ----------------
__global__ void init_kernel() {
    g_maxbits[0] = 0;
    g_maxbits[1] = 0;
}

__global__ void wmax_kernel(const float* __restrict__ w1, const float* __restrict__ w2) {
    const float* w = blockIdx.y ? w2 : w1;
    float mx = 0.f;
    for (int i = blockIdx.x * blockDim.x + threadIdx.x; i < KW_ELEM;
         i += gridDim.x * blockDim.x)
        mx = fmaxf(mx, fabsf(tanhf(w[i])));
#pragma unroll
    for (int o = 16; o; o >>= 1)
        mx = fmaxf(mx, __shfl_xor_sync(0xffffffffu, mx, o));
    if ((threadIdx.x & 31) == 0)
        atomicMax(&g_maxbits[blockIdx.y], __float_as_int(mx));
}

__global__ void wquant_kernel(const float* __restrict__ w1, const float* __restrict__ w2) {
    int which = blockIdx.y;
    const float* w = which ? w2 : w1;
    uint8_t* dst = which ? g_wq2 : g_wq1;
    float mx = __int_as_float(g_maxbits[which]);
    float s = 1.f / (2.f * mx);
    int i = blockIdx.x * blockDim.x + threadIdx.x;
    if (i >= KW_ELEM) return;
    float wn = tanhf(w[i]) * s + 0.5f;
    int q = (int)rintf(wn * 3.f);
    int co = i / 2304;
    int r = i % 2304;
    int ci = r / 9;
    int tap = r % 9;
    dst[co * 2304 + tap * 256 + ci] = (uint8_t)__byte_perm(WQ_TABLE, 0, q);
}

// BN1 + ReLU + 2-bit quant (*3) + NCHW -> NHWC e4m3
__global__ void actprep_kernel(const float* __restrict__ x,
                               const float* __restrict__ g1, const float* __restrict__ b1,
                               const float* __restrict__ m1, const float* __restrict__ v1) {
    __shared__ float ivs[256], bis[256];
    __shared__ __align__(16) uint8_t tile[56 * 260];
    int t = threadIdx.x;
    if (t < 256) {
        float iv = g1[t] / sqrtf(v1[t] + EPSF);
        ivs[t] = iv;
        bis[t] = b1[t] - m1[t] * iv;
    }
    __syncthreads();
    int nb = blockIdx.x;
    int n = nb / 56, y = nb % 56;
    const float* xr = x + (size_t)n * 256 * HW + y * 56;
    for (int idx = t; idx < 256 * 56; idx += blockDim.x) {
        int c = idx / 56, xx = idx % 56;
        float h = xr[(size_t)c * HW + xx] * ivs[c] + bis[c];
        h = fminf(fmaxf(h, 0.f), 1.f);
        int q = (int)rintf(h * 3.f);
        tile[xx * 260 + c] = (uint8_t)__byte_perm(ACT_TABLE, 0, q);
    }
    __syncthreads();
    uint32_t* o = (uint32_t*)(g_act0 + (size_t)((n * 56 + y) * 56) * 256);
    for (int idx = t; idx < 56 * 64; idx += blockDim.x) {
        int xx = idx >> 6, cq = idx & 63;
        o[xx * 64 + cq] = *(const uint32_t*)&tile[xx * 260 + cq * 4];
    }
}

// ---------------- implicit-GEMM conv3x3 via mma.sync (fp8 m16n8k32 e4m3 -> f32) ----------------
// CTA: 128 px x 256 co.  K = 2304, 36 double-buffered stages of 64B (tap = s/4, quarter = s%4).
// 16 warps, each a 32(M) x 64(N) warp tile.  SMEM rows padded to 80B (conflict-free ldmatrix).
#define CONV_SMEM 63488
#define A_STRIDE 80
#define A_BUF 10240
#define B_BASE 20480
#define B_BUF 20480

__global__ __launch_bounds__(512, 1)
void conv_qmma_kernel(int phase,
                      const float* __restrict__ g2, const float* __restrict__ b2,
                      const float* __restrict__ m2, const float* __restrict__ v2,
                      const float* __restrict__ xin, float* __restrict__ out) {
    extern __shared__ __align__(128) uint8_t smem[];
    float* ivs = (float*)(smem + 61440);
    float* bis = (float*)(smem + 62464);
    const uint32_t sbase = smem_u32(smem);

    const uint8_t* __restrict__ Ag = (phase == 1) ? g_act0 : g_act1;
    const uint8_t* __restrict__ Bg = (phase == 1) ? g_wq1 : g_wq2;

    const int t = threadIdx.x;
    const int wid = t >> 5, lid = t & 31;
    const int wm = wid & 3, wn = wid >> 2;       // warp grid 4(M) x 4(N)
    const int g = lid >> 2, tig = lid & 3;

    if (phase == 1 && t < 256) {
        float iv = g2[t] / sqrtf(v2[t] + EPSF);
        ivs[t] = iv;
        bis[t] = b2[t] - m2[t] * iv;
    }

    const int arow = t >> 2, aq = t & 3;         // A: 128 rows x 4 x 16B
    const int pm = blockIdx.x * 128 + arow;
    const int an = pm / HW;
    const int ar = pm - an * HW;
    const int ay = ar / 56, ax = ar - (ar / 56) * 56;
    const int brow = t >> 1, bh = t & 1;         // B: 256 rows x 2 x 32B
    const uint8_t* __restrict__ bb = Bg + brow * 2304;

    int4 la, lb0, lb1;
    auto LDG = [&](int s) {
        int tap = s >> 2, q = s & 3;
        int ty = tap / 3, tx = tap - ty * 3;
        int yy = ay + ty - 1, xx = ax + tx - 1;
        if (yy >= 0 && yy < 56 && xx >= 0 && xx < 56)
            la = *(const int4*)(Ag + (size_t)((an * 56 + yy) * 56 + xx) * 256 + q * 64 + aq * 16);
        else
            la = make_int4(0, 0, 0, 0);
        const uint8_t* bp = bb + tap * 256 + q * 64 + bh * 32;
        lb0 = ((const int4*)bp)[0];
        lb1 = ((const int4*)bp)[1];
    };
    auto STS = [&](int buf) {
        *(int4*)(smem + buf * A_BUF + arow * A_STRIDE + aq * 16) = la;
        uint8_t* bq = smem + B_BASE + buf * B_BUF + brow * A_STRIDE + bh * 32;
        ((int4*)bq)[0] = lb0;
        ((int4*)bq)[1] = lb1;
    };

    uint32_t aoff[2];
#pragma unroll
    for (int i = 0; i < 2; i++)
        aoff[i] = (uint32_t)((wm * 32 + i * 16 + (lid & 15)) * A_STRIDE + (lid >> 4) * 16);
    uint32_t boff[4];
#pragma unroll
    for (int j = 0; j < 4; j++)
        boff[j] = (uint32_t)((wn * 64 + j * 16 + (lid & 7) + ((lid >> 4) & 1) * 8) * A_STRIDE +
                             ((lid >> 3) & 1) * 16);

    float acc[2][8][4];
#pragma unroll
    for (int i = 0; i < 2; i++)
#pragma unroll
        for (int n = 0; n < 8; n++)
#pragma unroll
            for (int c = 0; c < 4; c++) acc[i][n][c] = 0.f;

    auto COMP = [&](int buf) {
        uint32_t ab = sbase + buf * A_BUF;
        uint32_t bbs = sbase + B_BASE + buf * B_BUF;
#pragma unroll
        for (int ks = 0; ks < 2; ks++) {
            uint32_t afr[2][4];
#pragma unroll
            for (int i = 0; i < 2; i++)
                ldsm_x4(afr[i][0], afr[i][1], afr[i][2], afr[i][3],
                        ab + aoff[i] + ks * 32);
#pragma unroll
            for (int j = 0; j < 4; j++) {
                uint32_t b0, b1, b2_, b3;
                ldsm_x4(b0, b1, b2_, b3, bbs + boff[j] + ks * 32);
#pragma unroll
                for (int i = 0; i < 2; i++) {
                    qmma16832(acc[i][j * 2 + 0], afr[i], b0, b1);
                    qmma16832(acc[i][j * 2 + 1], afr[i], b2_, b3);
                }
            }
        }
    };

    LDG(0);
    STS(0);
    __syncthreads();
#pragma unroll 1
    for (int s = 0; s < 36; s++) {
        if (s < 35) LDG(s + 1);
        COMP(s & 1);
        if (s < 35) STS((s + 1) & 1);
        __syncthreads();
    }

    const int pm0 = blockIdx.x * 128 + wm * 32 + g;
    const int c0 = wn * 64 + tig * 2;

    if (phase == 1) {
#pragma unroll
        for (int i = 0; i < 2; i++)
#pragma unroll
            for (int h = 0; h < 2; h++) {
                int px = pm0 + i * 16 + h * 8;
                uint8_t* dst = g_act1 + (size_t)px * 256 + c0;
#pragma unroll
                for (int nt = 0; nt < 8; nt++) {
                    int c = c0 + nt * 8;
                    float v0 = acc[i][nt][h * 2 + 0] * (1.f / 9.f) * ivs[c] + bis[c];
                    float v1 = acc[i][nt][h * 2 + 1] * (1.f / 9.f) * ivs[c + 1] + bis[c + 1];
                    v0 = fminf(fmaxf(v0, 0.f), 1.f);
                    v1 = fminf(fmaxf(v1, 0.f), 1.f);
                    int q0 = (int)rintf(v0 * 3.f);
                    int q1 = (int)rintf(v1 * 3.f);
                    uchar2 pk;
                    pk.x = (uint8_t)__byte_perm(ACT_TABLE, 0, q0);
                    pk.y = (uint8_t)__byte_perm(ACT_TABLE, 0, q1);
                    *(uchar2*)(dst + nt * 8) = pk;
                }
            }
    } else {
#pragma unroll
        for (int i = 0; i < 2; i++)
#pragma unroll
            for (int h = 0; h < 2; h++) {
                int px = pm0 + i * 16 + h * 8;
                int nn = px / HW;
                int rr = px - nn * HW;
                const float* xp = xin + (size_t)nn * 256 * HW + rr;
                float* op = out + (size_t)nn * 256 * HW + rr;
#pragma unroll
                for (int nt = 0; nt < 8; nt++) {
                    int c = c0 + nt * 8;
                    size_t o0 = (size_t)c * HW;
                    size_t o1 = (size_t)(c + 1) * HW;
                    op[o0] = acc[i][nt][h * 2 + 0] * (1.f / 9.f) + xp[o0];
                    op[o1] = acc[i][nt][h * 2 + 1] * (1.f / 9.f) + xp[o1];
                }
            }
    }
}

// ---------------- launch ----------------
extern "C" void kernel_launch(void* const* d_in, const int* in_sizes, int n_in,
                              void* d_out, int out_size) {
    const float* x  = (const float*)d_in[0];
    const float* w1 = (const float*)d_in[1];
    const float* w2 = (const float*)d_in[2];
    const float* g1 = (const float*)d_in[3];
    const float* b1 = (const float*)d_in[4];
    const float* m1 = (const float*)d_in[5];
    const float* v1 = (const float*)d_in[6];
    const float* g2 = (const float*)d_in[7];
    const float* b2 = (const float*)d_in[8];
    const float* m2 = (const float*)d_in[9];
    const float* v2 = (const float*)d_in[10];
    float* out = (float*)d_out;
    (void)in_sizes; (void)n_in; (void)out_size;

    cudaFuncSetAttribute(conv_qmma_kernel,
                         cudaFuncAttributeMaxDynamicSharedMemorySize, CONV_SMEM);

    init_kernel<<<1, 1>>>();
    wmax_kernel<<<dim3(128, 2), 256>>>(w1, w2);
    wquant_kernel<<<dim3(2304, 2), 256>>>(w1, w2);
    actprep_kernel<<<32 * 56, 256>>>(x, g1, b1, m1, v1);
    conv_qmma_kernel<<<784, 512, CONV_SMEM>>>(1, g2, b2, m2, v2, x, out);
    conv_qmma_kernel<<<784, 512, CONV_SMEM>>>(2, g2, b2, m2, v2, x, out);
}

// round 7
// speedup vs baseline: 2.6317x; 1.0240x over previous
#include <cuda_runtime.h>
#include <cuda_fp16.h>
#include <cstdint>

#define EPSF 1e-5f
#define HW 3136                  // 56*56
#define M_TOT 100352             // 32*56*56
#define NTILES 25088             // 32*28*28  (2x2 output tiles)
#define KW_ELEM 589824           // 256*256*3*3

// fp16 codes for quantized activation values {0,1,2,3}
__device__ __constant__ uint16_t ACTH[4] = {0x0000, 0x3C00, 0x4000, 0x4200};

// Output-transform coefficients per t=(a*4+b): {c00,c01,c10,c11} = AT0[a]AT0[b],AT0[a]AT1[b],AT1[a]AT0[b],AT1[a]AT1[b]
// AT0 = {1,1,1,0}, AT1 = {0,1,-1,-1}
__device__ __constant__ float4 WCOEF[16] = {
    {1, 0, 0, 0}, {1, 1, 0, 0}, {1, -1, 0, 0}, {0, -1, 0, 0},
    {1, 0, 1, 0}, {1, 1, 1, 1}, {1, -1, 1, -1}, {0, -1, 0, -1},
    {1, 0, -1, 0}, {1, 1, -1, -1}, {1, -1, -1, 1}, {0, -1, 0, 1},
    {0, 0, -1, 0}, {0, 0, -1, -1}, {0, 0, -1, 1}, {0, 0, 0, 1}};

// ---------------- static device scratch ----------------
__device__ int g_maxbits[2];
__device__ __align__(128) __half g_U1[16 * 256 * 256];           // U[t][co][ci]
__device__ __align__(128) __half g_U2[16 * 256 * 256];
__device__ __align__(128) __half g_act0[(size_t)M_TOT * 256];    // NHWC fp16, acts*3
__device__ __align__(128) __half g_act1[(size_t)M_TOT * 256];
__device__ __align__(128) __half g_V[(size_t)16 * NTILES * 256]; // V[t][tile][ci]

__device__ __forceinline__ uint32_t smem_u32(const void* p) {
    uint32_t a;
    asm("{ .reg .u64 t; cvta.to.shared.u64 t, %1; cvt.u32.u64 %0, t; }" : "=r"(a) : "l"(p));
    return a;
}

__device__ __forceinline__ void ldsm_x4(uint32_t& f0, uint32_t& f1, uint32_t& f2,
                                        uint32_t& f3, uint32_t addr) {
    asm volatile("ldmatrix.sync.aligned.m8n8.x4.shared.b16 {%0,%1,%2,%3}, [%4];"
                 : "=r"(f0), "=r"(f1), "=r"(f2), "=r"(f3) : "r"(addr));
}

__device__ __forceinline__ void hmma16816(float* c, const uint32_t* a, uint32_t b0, uint32_t b1) {
    asm volatile(
        "mma.sync.aligned.m16n8k16.row.col.f32.f16.f16.f32 "
        "{%0,%1,%2,%3}, {%4,%5,%6,%7}, {%8,%9}, {%0,%1,%2,%3};"
        : "+f"(c[0]), "+f"(c[1]), "+f"(c[2]), "+f"(c[3])
        : "r"(a[0]), "r"(a[1]), "r"(a[2]), "r"(a[3]), "r"(b0), "r"(b1));
}

// ---------------- prep kernels ----------------
__global__ void init_kernel() {
    g_maxbits[0] = 0;
    g_maxbits[1] = 0;
}

__global__ void wmax_kernel(const float* __restrict__ w1, const float* __restrict__ w2) {
    const float* w = blockIdx.y ? w2 : w1;
    float mx = 0.f;
    for (int i = blockIdx.x * blockDim.x + threadIdx.x; i < KW_ELEM;
         i += gridDim.x * blockDim.x)
        mx = fmaxf(mx, fabsf(tanhf(w[i])));
#pragma unroll
    for (int o = 16; o; o >>= 1)
        mx = fmaxf(mx, __shfl_xor_sync(0xffffffffu, mx, o));
    if ((threadIdx.x & 31) == 0)
        atomicMax(&g_maxbits[blockIdx.y], __float_as_int(mx));
}

// DoReFa weight quant (*3) fused with Winograd weight transform U = G w G^T
// block = one co (256 threads = ci), grid = (256, 2)
__global__ void utrans_kernel(const float* __restrict__ w1, const float* __restrict__ w2) {
    __shared__ float ws[2304];
    int which = blockIdx.y;
    const float* w = which ? w2 : w1;
    __half* U = which ? g_U2 : g_U1;
    int co = blockIdx.x, t = threadIdx.x;
    for (int i = t; i < 2304; i += 256) ws[i] = w[(size_t)co * 2304 + i];
    __syncthreads();
    float s = 1.f / (2.f * __int_as_float(g_maxbits[which]));
    float g[3][3];
#pragma unroll
    for (int i = 0; i < 3; i++)
#pragma unroll
        for (int j = 0; j < 3; j++) {
            float q = rintf((tanhf(ws[t * 9 + i * 3 + j]) * s + 0.5f) * 3.f);
            g[i][j] = 2.f * q - 3.f;                 // {-3,-1,1,3}
        }
    float r[4][3];
#pragma unroll
    for (int j = 0; j < 3; j++) {
        r[0][j] = g[0][j];
        r[1][j] = 0.5f * (g[0][j] + g[1][j] + g[2][j]);
        r[2][j] = 0.5f * (g[0][j] - g[1][j] + g[2][j]);
        r[3][j] = g[2][j];
    }
#pragma unroll
    for (int a = 0; a < 4; a++) {
        float u0 = r[a][0];
        float u1 = 0.5f * (r[a][0] + r[a][1] + r[a][2]);
        float u2 = 0.5f * (r[a][0] - r[a][1] + r[a][2]);
        float u3 = r[a][2];
        size_t base = ((size_t)(a * 4) * 256 + co) * 256 + t;
        size_t tstr = (size_t)256 * 256;
        U[base + 0 * tstr] = __float2half_rn(u0);
        U[base + 1 * tstr] = __float2half_rn(u1);
        U[base + 2 * tstr] = __float2half_rn(u2);
        U[base + 3 * tstr] = __float2half_rn(u3);
    }
}

// BN1 + ReLU + 2-bit quant (*3) + NCHW -> NHWC fp16
__global__ void actprep_kernel(const float* __restrict__ x,
                               const float* __restrict__ g1, const float* __restrict__ b1,
                               const float* __restrict__ m1, const float* __restrict__ v1) {
    __shared__ float ivs[256], bis[256];
    __shared__ __align__(16) uint16_t tile[56 * 264];
    int t = threadIdx.x;
    if (t < 256) {
        float iv = g1[t] / sqrtf(v1[t] + EPSF);
        ivs[t] = iv;
        bis[t] = b1[t] - m1[t] * iv;
    }
    __syncthreads();
    int nb = blockIdx.x;
    int n = nb / 56, y = nb % 56;
    const float* xr = x + (size_t)n * 256 * HW + y * 56;
    for (int idx = t; idx < 256 * 56; idx += blockDim.x) {
        int c = idx / 56, xx = idx % 56;
        float h = xr[(size_t)c * HW + xx] * ivs[c] + bis[c];
        h = fminf(fmaxf(h, 0.f), 1.f);
        int q = (int)rintf(h * 3.f);
        tile[xx * 264 + c] = ACTH[q];
    }
    __syncthreads();
    uint4* o = (uint4*)(g_act0 + (size_t)((n * 56 + y) * 56) * 256);
    for (int idx = t; idx < 56 * 32; idx += blockDim.x) {
        int xx = idx >> 5, qq = idx & 31;
        o[xx * 32 + qq] = *(const uint4*)&tile[xx * 264 + qq * 8];
    }
}

// ---------------- Winograd input transform: act -> V[t][tile][ci] ----------------
// block 256 threads: 2 tiles/block, 128 ci-pairs each. grid = NTILES/2 = 12544
__global__ void vtrans_kernel(int which) {
    const __half* act = which ? g_act1 : g_act0;
    int tid = threadIdx.x;
    int tile = blockIdx.x * 2 + (tid >> 7);
    int cp = tid & 127;                       // ci pair index (2 ci)
    int n = tile / 784;
    int r = tile - n * 784;
    int ty = r / 28, tx = r - (r / 28) * 28;
    const uint32_t* ap = (const uint32_t*)act + cp;
    int y0 = 2 * ty - 1, x0 = 2 * tx - 1;
    __half2 d[4][4];
#pragma unroll
    for (int p = 0; p < 4; p++) {
        int y = y0 + p;
        bool yv = (y >= 0) && (y < 56);
#pragma unroll
        for (int q = 0; q < 4; q++) {
            int x = x0 + q;
            uint32_t v = 0;
            if (yv && x >= 0 && x < 56)
                v = ap[(size_t)((n * 56 + y) * 56 + x) * 128];
            d[p][q] = *reinterpret_cast<__half2*>(&v);
        }
    }
    __half2 e[4][4];
#pragma unroll
    for (int q = 0; q < 4; q++) {
        e[0][q] = __hsub2(d[0][q], d[2][q]);
        e[1][q] = __hadd2(d[1][q], d[2][q]);
        e[2][q] = __hsub2(d[2][q], d[1][q]);
        e[3][q] = __hsub2(d[1][q], d[3][q]);
    }
    uint32_t* vp = (uint32_t*)g_V + (size_t)tile * 128 + cp;
    const size_t tstr = (size_t)NTILES * 128;
#pragma unroll
    for (int a = 0; a < 4; a++) {
        __half2 v0 = __hsub2(e[a][0], e[a][2]);
        __half2 v1 = __hadd2(e[a][1], e[a][2]);
        __half2 v2 = __hsub2(e[a][2], e[a][1]);
        __half2 v3 = __hsub2(e[a][1], e[a][3]);
        vp[(size_t)(a * 4 + 0) * tstr] = *reinterpret_cast<uint32_t*>(&v0);
        vp[(size_t)(a * 4 + 1) * tstr] = *reinterpret_cast<uint32_t*>(&v1);
        vp[(size_t)(a * 4 + 2) * tstr] = *reinterpret_cast<uint32_t*>(&v2);
        vp[(size_t)(a * 4 + 3) * tstr] = *reinterpret_cast<uint32_t*>(&v3);
    }
}

// ---------------- Winograd batched GEMM + fused output transform ----------------
// CTA: 64 tiles x 128 co, all 16 transform points, K=256 per point.
// Flat 64-stage loop: s -> (t = s>>2, kc = s&3 : 64-ci chunk), double-buffered.
// After each t's 4 stages, fold the C fragments into 2x2 output accumulators.
#define A_STRIDE 144
#define A_BUFSZ 9216            // 64*144
#define B_BASE_OFF 18432
#define B_BUFSZ 18432           // 128*144
#define IVS_OFF 55296
#define BIS_OFF 56320
#define WG_SMEM 57344

__global__ __launch_bounds__(512, 1)
void wgemm_kernel(int phase,
                  const float* __restrict__ g2, const float* __restrict__ b2,
                  const float* __restrict__ m2, const float* __restrict__ v2,
                  const float* __restrict__ xin, float* __restrict__ out) {
    extern __shared__ __align__(128) uint8_t smem[];
    float* ivs = (float*)(smem + IVS_OFF);
    float* bis = (float*)(smem + BIS_OFF);
    const uint32_t sbase = smem_u32(smem);

    const uint8_t* __restrict__ Vb = (const uint8_t*)g_V;
    const uint8_t* __restrict__ Ub = (const uint8_t*)(phase == 1 ? g_U1 : g_U2);

    const int t = threadIdx.x;
    const int wid = t >> 5, lid = t & 31;
    const int wm = wid & 3, wn = wid >> 2;        // 4(M) x 4(N) warp grid
    const int g = lid >> 2, tig = lid & 3;

    const int tileb = blockIdx.x * 64;
    const int cob = blockIdx.y * 128;

    if (phase == 1 && t < 256) {
        float iv = g2[t] / sqrtf(v2[t] + EPSF);
        ivs[t] = iv;
        bis[t] = b2[t] - m2[t] * iv;
    }

    // loaders: A 64 rows x 8 segs(16B); B 128 rows x 4 double-segs(32B)
    const int arow = t >> 3, aseg = t & 7;
    const int brow = t >> 2, bcol = (t & 3) * 32;

    int4 la, lb0, lb1;
    auto LDG = [&](int s) {
        int tt = s >> 2, kc = s & 3;
        la = *(const int4*)(Vb + ((size_t)tt * NTILES + tileb + arow) * 512 +
                            kc * 128 + aseg * 16);
        const uint8_t* bp = Ub + ((size_t)tt * 256 + cob + brow) * 512 + kc * 128 + bcol;
        lb0 = ((const int4*)bp)[0];
        lb1 = ((const int4*)bp)[1];
    };
    auto STS = [&](int buf) {
        *(int4*)(smem + buf * A_BUFSZ + arow * A_STRIDE + aseg * 16) = la;
        uint8_t* q = smem + B_BASE_OFF + buf * B_BUFSZ + brow * A_STRIDE + bcol;
        ((int4*)q)[0] = lb0;
        ((int4*)q)[1] = lb1;
    };

    // ldmatrix per-lane offsets
    const uint32_t aoff = (uint32_t)((wm * 16 + (lid & 15)) * A_STRIDE + (lid >> 4) * 16);
    uint32_t boff[2];
#pragma unroll
    for (int j = 0; j < 2; j++)
        boff[j] = (uint32_t)((wn * 32 + j * 16 + (lid & 7) + ((lid >> 4) & 1) * 8) * A_STRIDE +
                             ((lid >> 3) & 1) * 16);

    float fr[4][4];
#pragma unroll
    for (int n = 0; n < 4; n++)
#pragma unroll
        for (int c = 0; c < 4; c++) fr[n][c] = 0.f;

    float O_[2][4][2][4];
#pragma unroll
    for (int a = 0; a < 2; a++)
#pragma unroll
        for (int b = 0; b < 4; b++)
#pragma unroll
            for (int c = 0; c < 2; c++)
#pragma unroll
                for (int d = 0; d < 4; d++) O_[a][b][c][d] = 0.f;

    auto COMP = [&](int buf) {
        uint32_t ab = sbase + buf * A_BUFSZ;
        uint32_t bb = sbase + B_BASE_OFF + buf * B_BUFSZ;
#pragma unroll
        for (int ks = 0; ks < 4; ks++) {
            uint32_t A[4];
            ldsm_x4(A[0], A[1], A[2], A[3], ab + aoff + ks * 32);
#pragma unroll
            for (int j = 0; j < 2; j++) {
                uint32_t b0, b1, b2_, b3;
                ldsm_x4(b0, b1, b2_, b3, bb + boff[j] + ks * 32);
                hmma16816(fr[j * 2 + 0], A, b0, b1);
                hmma16816(fr[j * 2 + 1], A, b2_, b3);
            }
        }
    };

    LDG(0);
    STS(0);
    __syncthreads();
#pragma unroll 1
    for (int s = 0; s < 64; s++) {
        if (s < 63) LDG(s + 1);
        COMP(s & 1);
        if (s < 63) STS((s + 1) & 1);
        if ((s & 3) == 3) {
            float4 cc = WCOEF[s >> 2];
#pragma unroll
            for (int nf = 0; nf < 4; nf++)
#pragma unroll
                for (int ti = 0; ti < 2; ti++)
#pragma unroll
                    for (int cci = 0; cci < 2; cci++) {
                        float m = fr[nf][ti * 2 + cci];
                        O_[ti][nf][cci][0] += cc.x * m;
                        O_[ti][nf][cci][1] += cc.y * m;
                        O_[ti][nf][cci][2] += cc.z * m;
                        O_[ti][nf][cci][3] += cc.w * m;
                    }
#pragma unroll
            for (int n = 0; n < 4; n++)
#pragma unroll
                for (int c = 0; c < 4; c++) fr[n][c] = 0.f;
        }
        __syncthreads();
    }

    // ---------------- epilogue ----------------
#pragma unroll
    for (int ti = 0; ti < 2; ti++) {
        int tglob = tileb + wm * 16 + g + ti * 8;
        int n = tglob / 784;
        int r = tglob - n * 784;
        int ty = r / 28, tx = r - (r / 28) * 28;
        int y0 = 2 * ty, x0 = 2 * tx;

        if (phase == 1) {
#pragma unroll
            for (int py = 0; py < 2; py++)
#pragma unroll
                for (int px = 0; px < 2; px++) {
                    size_t pix = (size_t)((n * 56 + y0 + py) * 56 + x0 + px) * 256;
#pragma unroll
                    for (int nf = 0; nf < 4; nf++) {
                        int c = cob + wn * 32 + nf * 8 + tig * 2;
                        float v0 = O_[ti][nf][0][py * 2 + px] * (1.f / 9.f) * ivs[c] + bis[c];
                        float v1 = O_[ti][nf][1][py * 2 + px] * (1.f / 9.f) * ivs[c + 1] + bis[c + 1];
                        v0 = fminf(fmaxf(v0, 0.f), 1.f);
                        v1 = fminf(fmaxf(v1, 0.f), 1.f);
                        int q0 = (int)rintf(v0 * 3.f);
                        int q1 = (int)rintf(v1 * 3.f);
                        uint32_t pk = (uint32_t)ACTH[q0] | ((uint32_t)ACTH[q1] << 16);
                        *(uint32_t*)((uint16_t*)g_act1 + pix + c) = pk;
                    }
                }
        } else {
#pragma unroll
            for (int nf = 0; nf < 4; nf++)
#pragma unroll
                for (int cci = 0; cci < 2; cci++) {
                    int c = cob + wn * 32 + nf * 8 + tig * 2 + cci;
                    size_t base = ((size_t)n * 256 + c) * HW;
#pragma unroll
                    for (int py = 0; py < 2; py++) {
                        size_t idx = base + (size_t)(y0 + py) * 56 + x0;
                        out[idx] = O_[ti][nf][cci][py * 2 + 0] * (1.f / 9.f) + xin[idx];
                        out[idx + 1] = O_[ti][nf][cci][py * 2 + 1] * (1.f / 9.f) + xin[idx + 1];
                    }
                }
        }
    }
}

// ---------------- launch ----------------
extern "C" void kernel_launch(void* const* d_in, const int* in_sizes, int n_in,
                              void* d_out, int out_size) {
    const float* x  = (const float*)d_in[0];
    const float* w1 = (const float*)d_in[1];
    const float* w2 = (const float*)d_in[2];
    const float* g1 = (const float*)d_in[3];
    const float* b1 = (const float*)d_in[4];
    const float* m1 = (const float*)d_in[5];
    const float* v1 = (const float*)d_in[6];
    const float* g2 = (const float*)d_in[7];
    const float* b2 = (const float*)d_in[8];
    const float* m2 = (const float*)d_in[9];
    const float* v2 = (const float*)d_in[10];
    float* out = (float*)d_out;
    (void)in_sizes; (void)n_in; (void)out_size;

    cudaFuncSetAttribute(wgemm_kernel,
                         cudaFuncAttributeMaxDynamicSharedMemorySize, WG_SMEM);

    init_kernel<<<1, 1>>>();
    wmax_kernel<<<dim3(128, 2), 256>>>(w1, w2);
    utrans_kernel<<<dim3(256, 2), 256>>>(w1, w2);
    actprep_kernel<<<32 * 56, 256>>>(x, g1, b1, m1, v1);
    vtrans_kernel<<<NTILES / 2, 256>>>(0);
    wgemm_kernel<<<dim3(392, 2), 512, WG_SMEM>>>(1, g2, b2, m2, v2, x, out);
    vtrans_kernel<<<NTILES / 2, 256>>>(1);
    wgemm_kernel<<<dim3(392, 2), 512, WG_SMEM>>>(2, g2, b2, m2, v2, x, out);
}

// round 8
// speedup vs baseline: 2.9120x; 1.1065x over previous
#include <cuda_runtime.h>
#include <cuda_fp16.h>
#include <cstdint>

#define EPSF 1e-5f
#define HW 3136                  // 56*56
#define M_TOT 100352             // 32*56*56
#define NTILES 25088             // 32*28*28  (2x2 output tiles)
#define KW_ELEM 589824           // 256*256*3*3

// fp16 codes for quantized activation values {0,1,2,3}
__device__ __constant__ uint16_t ACTH[4] = {0x0000, 0x3C00, 0x4000, 0x4200};

// Output-transform coefficients per t=(a*4+b): {c00,c01,c10,c11}
// AT0 = {1,1,1,0}, AT1 = {0,1,-1,-1}
__device__ __constant__ float4 WCOEF[16] = {
    {1, 0, 0, 0}, {1, 1, 0, 0}, {1, -1, 0, 0}, {0, -1, 0, 0},
    {1, 0, 1, 0}, {1, 1, 1, 1}, {1, -1, 1, -1}, {0, -1, 0, -1},
    {1, 0, -1, 0}, {1, 1, -1, -1}, {1, -1, -1, 1}, {0, -1, 0, 1},
    {0, 0, -1, 0}, {0, 0, -1, -1}, {0, 0, -1, 1}, {0, 0, 0, 1}};

// ---------------- static device scratch ----------------
__device__ int g_maxbits[2];
__device__ __align__(128) __half g_U1[16 * 256 * 256];            // U[t][co][ci] fp16
__device__ __align__(128) __half g_U2[16 * 256 * 256];
__device__ __align__(128) __half g_act0[(size_t)M_TOT * 256];     // NHWC fp16, acts*3
__device__ __align__(128) __half g_act1[(size_t)M_TOT * 256];
__device__ __align__(128) uint8_t g_V[(size_t)16 * NTILES * 256]; // V[t][tile][ci] e4m3 (ints |v|<=12, exact)

__device__ __forceinline__ uint32_t smem_u32(const void* p) {
    uint32_t a;
    asm("{ .reg .u64 t; cvta.to.shared.u64 t, %1; cvt.u32.u64 %0, t; }" : "=r"(a) : "l"(p));
    return a;
}

__device__ __forceinline__ void ldsm_x4(uint32_t& f0, uint32_t& f1, uint32_t& f2,
                                        uint32_t& f3, uint32_t addr) {
    asm volatile("ldmatrix.sync.aligned.m8n8.x4.shared.b16 {%0,%1,%2,%3}, [%4];"
                 : "=r"(f0), "=r"(f1), "=r"(f2), "=r"(f3) : "r"(addr));
}

__device__ __forceinline__ void hmma16816(float* c, const uint32_t* a, uint32_t b0, uint32_t b1) {
    asm volatile(
        "mma.sync.aligned.m16n8k16.row.col.f32.f16.f16.f32 "
        "{%0,%1,%2,%3}, {%4,%5,%6,%7}, {%8,%9}, {%0,%1,%2,%3};"
        : "+f"(c[0]), "+f"(c[1]), "+f"(c[2]), "+f"(c[3])
        : "r"(a[0]), "r"(a[1]), "r"(a[2]), "r"(a[3]), "r"(b0), "r"(b1));
}

// e4m3x2 (packed in low 16 bits) -> f16x2 ; exact for small integers
__device__ __forceinline__ uint32_t cvt_e4m3x2_f16x2(uint32_t v) {
    uint32_t r;
    asm("cvt.rn.f16x2.e4m3x2 %0, %1;" : "=r"(r) : "h"((uint16_t)v));
    return r;
}
// f16x2 -> e4m3x2 (returned in low 16 bits) ; exact for ints |v|<=16
__device__ __forceinline__ uint32_t cvt_f16x2_e4m3x2(__half2 h) {
    uint16_t r;
    asm("cvt.rn.satfinite.e4m3x2.f16x2 %0, %1;"
        : "=h"(r) : "r"(*reinterpret_cast<uint32_t*>(&h)));
    return (uint32_t)r;
}

// ---------------- prep kernels ----------------
__global__ void init_kernel() {
    g_maxbits[0] = 0;
    g_maxbits[1] = 0;
}

__global__ void wmax_kernel(const float* __restrict__ w1, const float* __restrict__ w2) {
    const float* w = blockIdx.y ? w2 : w1;
    float mx = 0.f;
    for (int i = blockIdx.x * blockDim.x + threadIdx.x; i < KW_ELEM;
         i += gridDim.x * blockDim.x)
        mx = fmaxf(mx, fabsf(tanhf(w[i])));
#pragma unroll
    for (int o = 16; o; o >>= 1)
        mx = fmaxf(mx, __shfl_xor_sync(0xffffffffu, mx, o));
    if ((threadIdx.x & 31) == 0)
        atomicMax(&g_maxbits[blockIdx.y], __float_as_int(mx));
}

// DoReFa weight quant (*3) fused with Winograd weight transform U = G w G^T (fp16, exact)
__global__ void utrans_kernel(const float* __restrict__ w1, const float* __restrict__ w2) {
    __shared__ float ws[2304];
    int which = blockIdx.y;
    const float* w = which ? w2 : w1;
    __half* U = which ? g_U2 : g_U1;
    int co = blockIdx.x, t = threadIdx.x;
    for (int i = t; i < 2304; i += 256) ws[i] = w[(size_t)co * 2304 + i];
    __syncthreads();
    float s = 1.f / (2.f * __int_as_float(g_maxbits[which]));
    float g[3][3];
#pragma unroll
    for (int i = 0; i < 3; i++)
#pragma unroll
        for (int j = 0; j < 3; j++) {
            float q = rintf((tanhf(ws[t * 9 + i * 3 + j]) * s + 0.5f) * 3.f);
            g[i][j] = 2.f * q - 3.f;                 // {-3,-1,1,3}
        }
    float r[4][3];
#pragma unroll
    for (int j = 0; j < 3; j++) {
        r[0][j] = g[0][j];
        r[1][j] = 0.5f * (g[0][j] + g[1][j] + g[2][j]);
        r[2][j] = 0.5f * (g[0][j] - g[1][j] + g[2][j]);
        r[3][j] = g[2][j];
    }
#pragma unroll
    for (int a = 0; a < 4; a++) {
        float u0 = r[a][0];
        float u1 = 0.5f * (r[a][0] + r[a][1] + r[a][2]);
        float u2 = 0.5f * (r[a][0] - r[a][1] + r[a][2]);
        float u3 = r[a][2];
        size_t base = ((size_t)(a * 4) * 256 + co) * 256 + t;
        size_t tstr = (size_t)256 * 256;
        U[base + 0 * tstr] = __float2half_rn(u0);
        U[base + 1 * tstr] = __float2half_rn(u1);
        U[base + 2 * tstr] = __float2half_rn(u2);
        U[base + 3 * tstr] = __float2half_rn(u3);
    }
}

// BN1 + ReLU + 2-bit quant (*3) + NCHW -> NHWC fp16
__global__ void actprep_kernel(const float* __restrict__ x,
                               const float* __restrict__ g1, const float* __restrict__ b1,
                               const float* __restrict__ m1, const float* __restrict__ v1) {
    __shared__ float ivs[256], bis[256];
    __shared__ __align__(16) uint16_t tile[56 * 264];
    int t = threadIdx.x;
    if (t < 256) {
        float iv = g1[t] / sqrtf(v1[t] + EPSF);
        ivs[t] = iv;
        bis[t] = b1[t] - m1[t] * iv;
    }
    __syncthreads();
    int nb = blockIdx.x;
    int n = nb / 56, y = nb % 56;
    const float* xr = x + (size_t)n * 256 * HW + y * 56;
    for (int idx = t; idx < 256 * 56; idx += blockDim.x) {
        int c = idx / 56, xx = idx % 56;
        float h = xr[(size_t)c * HW + xx] * ivs[c] + bis[c];
        h = fminf(fmaxf(h, 0.f), 1.f);
        int q = (int)rintf(h * 3.f);
        tile[xx * 264 + c] = ACTH[q];
    }
    __syncthreads();
    uint4* o = (uint4*)(g_act0 + (size_t)((n * 56 + y) * 56) * 256);
    for (int idx = t; idx < 56 * 32; idx += blockDim.x) {
        int xx = idx >> 5, qq = idx & 31;
        o[xx * 32 + qq] = *(const uint4*)&tile[xx * 264 + qq * 8];
    }
}

// ---------------- Winograd input transform: act(fp16) -> V(e4m3) ----------------
// block 256 threads: 4 tiles/block, 64 threads/tile, 4 ci each. grid = NTILES/4
__global__ void vtrans_kernel(int which) {
    const __half* act = which ? g_act1 : g_act0;
    int tid = threadIdx.x;
    int tile = blockIdx.x * 4 + (tid >> 6);
    int cp = tid & 63;                        // 4-ci group
    int n = tile / 784;
    int r = tile - n * 784;
    int ty = r / 28, tx = r - (r / 28) * 28;
    const uint2* ap = (const uint2*)act + cp;
    int y0 = 2 * ty - 1, x0 = 2 * tx - 1;
    __half2 dl[4][4], dh[4][4];
#pragma unroll
    for (int p = 0; p < 4; p++) {
        int y = y0 + p;
        bool yv = (y >= 0) && (y < 56);
#pragma unroll
        for (int q = 0; q < 4; q++) {
            int x = x0 + q;
            uint2 v = make_uint2(0, 0);
            if (yv && x >= 0 && x < 56)
                v = ap[(size_t)((n * 56 + y) * 56 + x) * 64];
            dl[p][q] = *reinterpret_cast<__half2*>(&v.x);
            dh[p][q] = *reinterpret_cast<__half2*>(&v.y);
        }
    }
    __half2 el[4][4], eh[4][4];
#pragma unroll
    for (int q = 0; q < 4; q++) {
        el[0][q] = __hsub2(dl[0][q], dl[2][q]);
        el[1][q] = __hadd2(dl[1][q], dl[2][q]);
        el[2][q] = __hsub2(dl[2][q], dl[1][q]);
        el[3][q] = __hsub2(dl[1][q], dl[3][q]);
        eh[0][q] = __hsub2(dh[0][q], dh[2][q]);
        eh[1][q] = __hadd2(dh[1][q], dh[2][q]);
        eh[2][q] = __hsub2(dh[2][q], dh[1][q]);
        eh[3][q] = __hsub2(dh[1][q], dh[3][q]);
    }
    uint32_t* vp = (uint32_t*)g_V + (size_t)tile * 64 + cp;
    const size_t tstr = (size_t)NTILES * 64;
#pragma unroll
    for (int a = 0; a < 4; a++) {
        __half2 l0 = __hsub2(el[a][0], el[a][2]);
        __half2 l1 = __hadd2(el[a][1], el[a][2]);
        __half2 l2 = __hsub2(el[a][2], el[a][1]);
        __half2 l3 = __hsub2(el[a][1], el[a][3]);
        __half2 h0 = __hsub2(eh[a][0], eh[a][2]);
        __half2 h1 = __hadd2(eh[a][1], eh[a][2]);
        __half2 h2 = __hsub2(eh[a][2], eh[a][1]);
        __half2 h3 = __hsub2(eh[a][1], eh[a][3]);
        vp[(size_t)(a * 4 + 0) * tstr] = cvt_f16x2_e4m3x2(l0) | (cvt_f16x2_e4m3x2(h0) << 16);
        vp[(size_t)(a * 4 + 1) * tstr] = cvt_f16x2_e4m3x2(l1) | (cvt_f16x2_e4m3x2(h1) << 16);
        vp[(size_t)(a * 4 + 2) * tstr] = cvt_f16x2_e4m3x2(l2) | (cvt_f16x2_e4m3x2(h2) << 16);
        vp[(size_t)(a * 4 + 3) * tstr] = cvt_f16x2_e4m3x2(l3) | (cvt_f16x2_e4m3x2(h3) << 16);
    }
}

// ---------------- Winograd batched GEMM (fp16 HMMA) + fused output transform ----------------
// CTA: 64 tiles x 128 co, 16 transform points, K=256/point; 64 double-buffered 64-ci stages.
// A loaded as e4m3 from g_V and converted to fp16 in-register before STS.
#define A_STRIDE 144
#define A_BUFSZ 9216            // 64*144
#define B_BASE_OFF 18432
#define B_BUFSZ 18432           // 128*144
#define IVS_OFF 55296
#define BIS_OFF 56320
#define WG_SMEM 57344

__global__ __launch_bounds__(512, 1)
void wgemm_kernel(int phase,
                  const float* __restrict__ g2, const float* __restrict__ b2,
                  const float* __restrict__ m2, const float* __restrict__ v2,
                  const float* __restrict__ xin, float* __restrict__ out) {
    extern __shared__ __align__(128) uint8_t smem[];
    float* ivs = (float*)(smem + IVS_OFF);
    float* bis = (float*)(smem + BIS_OFF);
    const uint32_t sbase = smem_u32(smem);

    const uint8_t* __restrict__ Vb = g_V;
    const uint8_t* __restrict__ Ub = (const uint8_t*)(phase == 1 ? g_U1 : g_U2);

    const int t = threadIdx.x;
    const int wid = t >> 5, lid = t & 31;
    const int wm = wid & 3, wn = wid >> 2;        // 4(M) x 4(N) warp grid
    const int g = lid >> 2, tig = lid & 3;

    const int cob = blockIdx.x * 128;             // x = co split (2) -> V-sharing CTAs adjacent
    const int tileb = blockIdx.y * 64;

    if (phase == 1 && t < 256) {
        float iv = g2[t] / sqrtf(v2[t] + EPSF);
        ivs[t] = iv;
        bis[t] = b2[t] - m2[t] * iv;
    }

    // loaders: A 64 rows x 8 segs(8B e4m3 -> 16B fp16); B 128 rows x 4 double-segs(32B)
    const int arow = t >> 3, aseg = t & 7;
    const int brow = t >> 2, bcol = (t & 3) * 32;

    uint2 la8;
    int4 lb0, lb1;
    auto LDG = [&](int s) {
        int tt = s >> 2, kc = s & 3;
        la8 = *(const uint2*)(Vb + ((size_t)tt * NTILES + tileb + arow) * 256 +
                              kc * 64 + aseg * 8);
        const uint8_t* bp = Ub + ((size_t)tt * 256 + cob + brow) * 512 + kc * 128 + bcol;
        lb0 = ((const int4*)bp)[0];
        lb1 = ((const int4*)bp)[1];
    };
    auto STS = [&](int buf) {
        int4 la;
        la.x = (int)cvt_e4m3x2_f16x2(la8.x & 0xFFFFu);
        la.y = (int)cvt_e4m3x2_f16x2(la8.x >> 16);
        la.z = (int)cvt_e4m3x2_f16x2(la8.y & 0xFFFFu);
        la.w = (int)cvt_e4m3x2_f16x2(la8.y >> 16);
        *(int4*)(smem + buf * A_BUFSZ + arow * A_STRIDE + aseg * 16) = la;
        uint8_t* q = smem + B_BASE_OFF + buf * B_BUFSZ + brow * A_STRIDE + bcol;
        ((int4*)q)[0] = lb0;
        ((int4*)q)[1] = lb1;
    };

    const uint32_t aoff = (uint32_t)((wm * 16 + (lid & 15)) * A_STRIDE + (lid >> 4) * 16);
    uint32_t boff[2];
#pragma unroll
    for (int j = 0; j < 2; j++)
        boff[j] = (uint32_t)((wn * 32 + j * 16 + (lid & 7) + ((lid >> 4) & 1) * 8) * A_STRIDE +
                             ((lid >> 3) & 1) * 16);

    float fr[4][4];
#pragma unroll
    for (int n = 0; n < 4; n++)
#pragma unroll
        for (int c = 0; c < 4; c++) fr[n][c] = 0.f;

    float O_[2][4][2][4];
#pragma unroll
    for (int a = 0; a < 2; a++)
#pragma unroll
        for (int b = 0; b < 4; b++)
#pragma unroll
            for (int c = 0; c < 2; c++)
#pragma unroll
                for (int d = 0; d < 4; d++) O_[a][b][c][d] = 0.f;

    auto COMP = [&](int buf) {
        uint32_t ab = sbase + buf * A_BUFSZ;
        uint32_t bb = sbase + B_BASE_OFF + buf * B_BUFSZ;
#pragma unroll
        for (int ks = 0; ks < 4; ks++) {
            uint32_t A[4];
            ldsm_x4(A[0], A[1], A[2], A[3], ab + aoff + ks * 32);
#pragma unroll
            for (int j = 0; j < 2; j++) {
                uint32_t b0, b1, b2_, b3;
                ldsm_x4(b0, b1, b2_, b3, bb + boff[j] + ks * 32);
                hmma16816(fr[j * 2 + 0], A, b0, b1);
                hmma16816(fr[j * 2 + 1], A, b2_, b3);
            }
        }
    };

    LDG(0);
    STS(0);
    __syncthreads();
#pragma unroll 1
    for (int s = 0; s < 64; s++) {
        if (s < 63) LDG(s + 1);
        COMP(s & 1);
        if (s < 63) STS((s + 1) & 1);
        if ((s & 3) == 3) {
            float4 cc = WCOEF[s >> 2];
#pragma unroll
            for (int nf = 0; nf < 4; nf++)
#pragma unroll
                for (int ti = 0; ti < 2; ti++)
#pragma unroll
                    for (int cci = 0; cci < 2; cci++) {
                        float m = fr[nf][ti * 2 + cci];
                        O_[ti][nf][cci][0] += cc.x * m;
                        O_[ti][nf][cci][1] += cc.y * m;
                        O_[ti][nf][cci][2] += cc.z * m;
                        O_[ti][nf][cci][3] += cc.w * m;
                    }
#pragma unroll
            for (int n = 0; n < 4; n++)
#pragma unroll
                for (int c = 0; c < 4; c++) fr[n][c] = 0.f;
        }
        __syncthreads();
    }

    // ---------------- epilogue ----------------
#pragma unroll
    for (int ti = 0; ti < 2; ti++) {
        int tglob = tileb + wm * 16 + g + ti * 8;
        int n = tglob / 784;
        int r = tglob - n * 784;
        int ty = r / 28, tx = r - (r / 28) * 28;
        int y0 = 2 * ty, x0 = 2 * tx;

        if (phase == 1) {
#pragma unroll
            for (int py = 0; py < 2; py++)
#pragma unroll
                for (int px = 0; px < 2; px++) {
                    size_t pix = (size_t)((n * 56 + y0 + py) * 56 + x0 + px) * 256;
#pragma unroll
                    for (int nf = 0; nf < 4; nf++) {
                        int c = cob + wn * 32 + nf * 8 + tig * 2;
                        float v0 = O_[ti][nf][0][py * 2 + px] * (1.f / 9.f) * ivs[c] + bis[c];
                        float v1 = O_[ti][nf][1][py * 2 + px] * (1.f / 9.f) * ivs[c + 1] + bis[c + 1];
                        v0 = fminf(fmaxf(v0, 0.f), 1.f);
                        v1 = fminf(fmaxf(v1, 0.f), 1.f);
                        int q0 = (int)rintf(v0 * 3.f);
                        int q1 = (int)rintf(v1 * 3.f);
                        uint32_t pk = (uint32_t)ACTH[q0] | ((uint32_t)ACTH[q1] << 16);
                        *(uint32_t*)((uint16_t*)g_act1 + pix + c) = pk;
                    }
                }
        } else {
#pragma unroll
            for (int nf = 0; nf < 4; nf++)
#pragma unroll
                for (int cci = 0; cci < 2; cci++) {
                    int c = cob + wn * 32 + nf * 8 + tig * 2 + cci;
                    size_t base = ((size_t)n * 256 + c) * HW;
#pragma unroll
                    for (int py = 0; py < 2; py++) {
                        size_t idx = base + (size_t)(y0 + py) * 56 + x0;
                        out[idx] = O_[ti][nf][cci][py * 2 + 0] * (1.f / 9.f) + xin[idx];
                        out[idx + 1] = O_[ti][nf][cci][py * 2 + 1] * (1.f / 9.f) + xin[idx + 1];
                    }
                }
        }
    }
}

// ---------------- launch ----------------
extern "C" void kernel_launch(void* const* d_in, const int* in_sizes, int n_in,
                              void* d_out, int out_size) {
    const float* x  = (const float*)d_in[0];
    const float* w1 = (const float*)d_in[1];
    const float* w2 = (const float*)d_in[2];
    const float* g1 = (const float*)d_in[3];
    const float* b1 = (const float*)d_in[4];
    const float* m1 = (const float*)d_in[5];
    const float* v1 = (const float*)d_in[6];
    const float* g2 = (const float*)d_in[7];
    const float* b2 = (const float*)d_in[8];
    const float* m2 = (const float*)d_in[9];
    const float* v2 = (const float*)d_in[10];
    float* out = (float*)d_out;
    (void)in_sizes; (void)n_in; (void)out_size;

    cudaFuncSetAttribute(wgemm_kernel,
                         cudaFuncAttributeMaxDynamicSharedMemorySize, WG_SMEM);

    init_kernel<<<1, 1>>>();
    wmax_kernel<<<dim3(128, 2), 256>>>(w1, w2);
    utrans_kernel<<<dim3(256, 2), 256>>>(w1, w2);
    actprep_kernel<<<32 * 56, 256>>>(x, g1, b1, m1, v1);
    vtrans_kernel<<<NTILES / 4, 256>>>(0);
    wgemm_kernel<<<dim3(2, 392), 512, WG_SMEM>>>(1, g2, b2, m2, v2, x, out);
    vtrans_kernel<<<NTILES / 4, 256>>>(1);
    wgemm_kernel<<<dim3(2, 392), 512, WG_SMEM>>>(2, g2, b2, m2, v2, x, out);
}